// round 13
// baseline (speedup 1.0000x reference)
#include <cuda_runtime.h>
#include <cuda_fp16.h>
#include <cstdint>
#include <cstddef>

#define C_CH 66
#define L_IN 100
#define BATCH 4096
#define FEAT 7128          // 9 * 66 * 12
#define KP   7168          // FEAT padded to 64
#define HID  1936
#define NP   2048          // HID padded to 128
#define NOUT 14

// ---------------------------------------------------------------------------
// Device-global scratch (allocation-free rule). .bss => zero-initialized; pad
// regions are never written, so K/N zero-padding is free and deterministic.
// ---------------------------------------------------------------------------
__device__ float  g_xt[(size_t)C_CH * L_IN * BATCH];   // x transposed (c,l,b)
__device__ __half g_fh[(size_t)BATCH * KP];            // feats (fp16)
__device__ __half g_w1h[(size_t)NP * KP];              // fw1 (fp16, padded)
__device__ float  g_h[(size_t)BATCH * HID];            // FC1 output

// ---------------------------------------------------------------------------
// PTX helpers (sm_80-era -> compile for plain compute_103)
// ---------------------------------------------------------------------------
__device__ __forceinline__ uint32_t smem_u32(const void* p) {
    uint32_t a;
    asm("{ .reg .u64 t; cvta.to.shared.u64 t, %1; cvt.u32.u64 %0, t; }" : "=r"(a) : "l"(p));
    return a;
}

#define CP16(saddr, gptr) \
    asm volatile("cp.async.cg.shared.global [%0], [%1], 16;" :: "r"(saddr), "l"(gptr) : "memory")
#define CP_COMMIT() asm volatile("cp.async.commit_group;" ::: "memory")
#define CP_WAIT2()  asm volatile("cp.async.wait_group 2;" ::: "memory")

#define LDSM4(r, addr) \
    asm volatile("ldmatrix.sync.aligned.m8n8.x4.shared.b16 {%0,%1,%2,%3}, [%4];" \
                 : "=r"((r)[0]), "=r"((r)[1]), "=r"((r)[2]), "=r"((r)[3]) : "r"(addr))
#define LDSM2(r, addr) \
    asm volatile("ldmatrix.sync.aligned.m8n8.x2.shared.b16 {%0,%1}, [%2];" \
                 : "=r"((r)[0]), "=r"((r)[1]) : "r"(addr))

__device__ __forceinline__ void mma16816(float* c, const uint32_t* a, const uint32_t* b) {
    asm volatile(
        "mma.sync.aligned.m16n8k16.row.col.f32.f16.f16.f32 "
        "{%0,%1,%2,%3}, {%4,%5,%6,%7}, {%8,%9}, {%0,%1,%2,%3};"
        : "+f"(c[0]), "+f"(c[1]), "+f"(c[2]), "+f"(c[3])
        : "r"(a[0]), "r"(a[1]), "r"(a[2]), "r"(a[3]), "r"(b[0]), "r"(b[1]));
}

// ---------------------------------------------------------------------------
// Kernel 0: transpose x (B,L,C) -> g_xt (C,L,B), tiled for coalescing.
// ---------------------------------------------------------------------------
__global__ __launch_bounds__(256)
void transpose_kernel(const float* __restrict__ x)
{
    __shared__ float tile[32][269];    // pad 264->269 (odd stride: conflict-free)
    const int b0 = blockIdx.x * 32;
    const int wid  = threadIdx.x >> 5;
    const int lane = threadIdx.x & 31;

    for (int l0 = 0; l0 < L_IN; l0 += 4) {
        for (int idx = threadIdx.x; idx < 32 * 264; idx += 256) {
            int bb = idx / 264, j = idx % 264;
            tile[bb][j] = x[((size_t)(b0 + bb) * L_IN + l0) * C_CH + j];
        }
        __syncthreads();
        for (int j = wid; j < 264; j += 8) {
            int lrel = j / C_CH, c = j % C_CH;
            g_xt[((size_t)c * L_IN + l0 + lrel) * BATCH + b0 + lane] = tile[lane][j];
        }
        __syncthreads();
    }
}

// ---------------------------------------------------------------------------
// Kernel 0b: convert fw1 to fp16 (padded to KP stride)
// ---------------------------------------------------------------------------
__global__ __launch_bounds__(256)
void wsplit_kernel(const float* __restrict__ fw1)
{
    size_t idx = (size_t)blockIdx.x * 256 + threadIdx.x;
    if (idx >= (size_t)HID * FEAT) return;
    int n = (int)(idx / FEAT);
    int k = (int)(idx % FEAT);
    g_w1h[(size_t)n * KP + k] = __float2half(fw1[idx]);
}

// ---------------------------------------------------------------------------
// Kernel 1: conv branches (R11-verified sliding-window version, unchanged)
// ---------------------------------------------------------------------------

// smem weight layout offsets (floats)
#define O_HW1 0
#define O_HB1 56
#define O_HW2 64
#define O_HB2 288
#define O_HW3 292
#define O_HB3 404
#define O_LW1 408
#define O_LB1 432
#define O_LW2 440
#define O_LB2 536
#define O_LW3 540
#define O_LB3 588
#define W_TOT 592

// dynamic smem layout (float offsets)
#define F_W   0
#define F_S   (F_W + W_TOT)              // 100 x 32
#define F_P1  (F_S + 100 * 32)           // 8 x 50 x 32
#define F_P2  (F_P1 + 8 * 50 * 32)       // 4 x 25 x 32
#define F_SF  (F_P2 + 4 * 25 * 32)       // 32 x 109 (staged output, pad 109)
#define F_TOT (F_SF + 32 * 109)          // 23280 floats = 93120 B
#define SM_FEATS (F_TOT * 4)

// layer1: 1 -> 8 channels, warp w handles out-channel o = w. S[100] -> P1[8][50].
template<int K, int PAD>
__device__ __forceinline__ void conv1_sl(
    const float* __restrict__ S, float* __restrict__ P1,
    const float* __restrict__ W, const float* __restrict__ Bv,
    int o, int lane)
{
    float wr[K], win[K];
    #pragma unroll
    for (int j = 0; j < K; j++) wr[j] = W[o * K + j];
    const float bias = Bv[o];
    #pragma unroll
    for (int j = 0; j < K; j++) {
        int p = j - PAD;
        win[j] = (p >= 0) ? S[p * 32 + lane] : 0.f;
    }
    for (int t = 0; t < 50; t++) {
        float r0 = bias;
        #pragma unroll
        for (int j = 0; j < K; j++) r0 += wr[j] * win[j];
        int nx0 = 2 * t + K - PAD;
        float nv0 = (nx0 < 100) ? S[nx0 * 32 + lane] : 0.f;
        #pragma unroll
        for (int j = 0; j < K - 1; j++) win[j] = win[j + 1];
        win[K - 1] = nv0;

        float r1 = bias;
        #pragma unroll
        for (int j = 0; j < K; j++) r1 += wr[j] * win[j];
        int nx1 = 2 * t + 1 + K - PAD;
        float nv1 = (nx1 < 100) ? S[nx1 * 32 + lane] : 0.f;
        #pragma unroll
        for (int j = 0; j < K - 1; j++) win[j] = win[j + 1];
        win[K - 1] = nv1;

        P1[(o * 50 + t) * 32 + lane] = 0.5f * (fmaxf(r0, 0.f) + fmaxf(r1, 0.f));
    }
}

// layers 2/3: CIN -> 4 channels, warp handles (o, t-range [t0, t0+TN)).
template<int K, int PAD, int CIN, int LIN, int TN>
__device__ __forceinline__ void convN_sl(
    const float* __restrict__ IN, const float* __restrict__ W,
    int o, int t0, int lane, float* __restrict__ acc0, float* __restrict__ acc1)
{
    constexpr int CH = 4;
    #pragma unroll
    for (int pass = 0; pass < CIN / CH; pass++) {
        float wr[CH][K], win[CH][K];
        #pragma unroll
        for (int ii = 0; ii < CH; ii++) {
            const int i = pass * CH + ii;
            #pragma unroll
            for (int j = 0; j < K; j++) wr[ii][j] = W[(o * CIN + i) * K + j];
            #pragma unroll
            for (int j = 0; j < K; j++) {
                int p = 2 * t0 - PAD + j;
                win[ii][j] = (p >= 0 && p < LIN) ? IN[(i * LIN + p) * 32 + lane] : 0.f;
            }
        }
        #pragma unroll
        for (int tt = 0; tt < TN; tt++) {
            float r0 = 0.f;
            #pragma unroll
            for (int ii = 0; ii < CH; ii++)
                #pragma unroll
                for (int j = 0; j < K; j++) r0 += wr[ii][j] * win[ii][j];
            acc0[tt] += r0;
            {
                int nx = 2 * (t0 + tt) + K - PAD;
                #pragma unroll
                for (int ii = 0; ii < CH; ii++) {
                    const int i = pass * CH + ii;
                    float nv = (nx < LIN) ? IN[(i * LIN + nx) * 32 + lane] : 0.f;
                    #pragma unroll
                    for (int j = 0; j < K - 1; j++) win[ii][j] = win[ii][j + 1];
                    win[ii][K - 1] = nv;
                }
            }
            float r1 = 0.f;
            #pragma unroll
            for (int ii = 0; ii < CH; ii++)
                #pragma unroll
                for (int j = 0; j < K; j++) r1 += wr[ii][j] * win[ii][j];
            acc1[tt] += r1;
            {
                int nx = 2 * (t0 + tt) + 1 + K - PAD;
                #pragma unroll
                for (int ii = 0; ii < CH; ii++) {
                    const int i = pass * CH + ii;
                    float nv = (nx < LIN) ? IN[(i * LIN + nx) * 32 + lane] : 0.f;
                    #pragma unroll
                    for (int j = 0; j < K - 1; j++) win[ii][j] = win[ii][j + 1];
                    win[ii][K - 1] = nv;
                }
            }
        }
    }
}

// layer2 wrapper: P1[8][50] -> P2[4][25]
template<int K, int PAD, int TN>
__device__ __forceinline__ void conv2_run(
    const float* __restrict__ P1, float* __restrict__ P2,
    const float* __restrict__ W, const float* __restrict__ Bv,
    int o, int t0, int lane)
{
    float a0[TN], a1[TN];
    #pragma unroll
    for (int i = 0; i < TN; i++) { a0[i] = 0.f; a1[i] = 0.f; }
    convN_sl<K, PAD, 8, 50, TN>(P1, W, o, t0, lane, a0, a1);
    const float bias = Bv[o];
    #pragma unroll
    for (int tt = 0; tt < TN; tt++)
        P2[(o * 25 + t0 + tt) * 32 + lane] =
            0.5f * (fmaxf(a0[tt] + bias, 0.f) + fmaxf(a1[tt] + bias, 0.f));
}

// layer3 wrapper: P2[4][25] -> sF[lane][base + o*12 + t]
template<int K, int PAD, int TN>
__device__ __forceinline__ void conv3_run(
    const float* __restrict__ P2, float* __restrict__ sF,
    const float* __restrict__ W, const float* __restrict__ Bv,
    int o, int t0, int lane, int base)
{
    float a0[TN], a1[TN];
    #pragma unroll
    for (int i = 0; i < TN; i++) { a0[i] = 0.f; a1[i] = 0.f; }
    convN_sl<K, PAD, 4, 25, TN>(P2, W, o, t0, lane, a0, a1);
    const float bias = Bv[o];
    #pragma unroll
    for (int tt = 0; tt < TN; tt++)
        sF[lane * 109 + base + o * 12 + t0 + tt] =
            0.5f * (fmaxf(a0[tt] + bias, 0.f) + fmaxf(a1[tt] + bias, 0.f));
}

__global__ __launch_bounds__(256, 2)
void feats_kernel(const float* __restrict__ hw1, const float* __restrict__ hb1,
                  const float* __restrict__ hw2, const float* __restrict__ hb2,
                  const float* __restrict__ hw3, const float* __restrict__ hb3,
                  const float* __restrict__ lw1, const float* __restrict__ lb1,
                  const float* __restrict__ lw2, const float* __restrict__ lb2,
                  const float* __restrict__ lw3, const float* __restrict__ lb3)
{
    extern __shared__ __align__(16) float sm[];
    float* sW  = sm + F_W;
    float* S   = sm + F_S;
    float* P1  = sm + F_P1;
    float* P2  = sm + F_P2;
    float* sF  = sm + F_SF;

    const int c   = blockIdx.x;
    const int b0  = blockIdx.y * 32;
    const int tid = threadIdx.x;
    const int wid  = tid >> 5;
    const int lane = tid & 31;

    // Phase 1: weights + signal
    { for (int i = tid; i < 56;  i += 256) sW[O_HW1 + i] = hw1[c * 56  + i]; }
    { for (int i = tid; i < 8;   i += 256) sW[O_HB1 + i] = hb1[c * 8   + i]; }
    { for (int i = tid; i < 224; i += 256) sW[O_HW2 + i] = hw2[c * 224 + i]; }
    { for (int i = tid; i < 4;   i += 256) sW[O_HB2 + i] = hb2[c * 4   + i]; }
    { for (int i = tid; i < 112; i += 256) sW[O_HW3 + i] = hw3[c * 112 + i]; }
    { for (int i = tid; i < 4;   i += 256) sW[O_HB3 + i] = hb3[c * 4   + i]; }
    { for (int i = tid; i < 24;  i += 256) sW[O_LW1 + i] = lw1[c * 24  + i]; }
    { for (int i = tid; i < 8;   i += 256) sW[O_LB1 + i] = lb1[c * 8   + i]; }
    { for (int i = tid; i < 96;  i += 256) sW[O_LW2 + i] = lw2[c * 96  + i]; }
    { for (int i = tid; i < 4;   i += 256) sW[O_LB2 + i] = lb2[c * 4   + i]; }
    { for (int i = tid; i < 48;  i += 256) sW[O_LW3 + i] = lw3[c * 48  + i]; }
    { for (int i = tid; i < 4;   i += 256) sW[O_LB3 + i] = lb3[c * 4   + i]; }
    for (int l = wid; l < L_IN; l += 8)
        S[l * 32 + lane] = g_xt[((size_t)c * L_IN + l) * BATCH + b0 + lane];
    __syncthreads();

    const int o4   = wid & 3;
    const int half = wid >> 2;

    // Phase 2: conv1 high
    conv1_sl<7, 3>(S, P1, sW + O_HW1, sW + O_HB1, wid, lane);
    __syncthreads();

    // Phase 3: conv2 high
    if (half == 0) conv2_run<7, 3, 13>(P1, P2, sW + O_HW2, sW + O_HB2, o4, 0,  lane);
    else           conv2_run<7, 3, 12>(P1, P2, sW + O_HW2, sW + O_HB2, o4, 13, lane);
    __syncthreads();

    // Phase 4: conv3 high + conv1 low + residual
    conv3_run<7, 3, 6>(P2, sF, sW + O_HW3, sW + O_HB3, o4, half * 6, lane, 0);
    conv1_sl<3, 1>(S, P1, sW + O_LW1, sW + O_LB1, wid, lane);
    for (int t = wid; t < 12; t += 8) {
        float s = 0.f;
        #pragma unroll
        for (int j = 0; j < 8; j++) s += S[(8 * t + j) * 32 + lane];
        sF[lane * 109 + 96 + t] = 0.125f * s;
    }
    __syncthreads();

    // Phase 5: conv2 low
    if (half == 0) conv2_run<3, 1, 13>(P1, P2, sW + O_LW2, sW + O_LB2, o4, 0,  lane);
    else           conv2_run<3, 1, 12>(P1, P2, sW + O_LW2, sW + O_LB2, o4, 13, lane);
    __syncthreads();

    // Phase 6: conv3 low
    conv3_run<3, 1, 6>(P2, sF, sW + O_LW3, sW + O_LB3, o4, half * 6, lane, 48);
    __syncthreads();

    // Phase 7: coalesced fp16 store
    for (int i = tid; i < 32 * 108; i += 256) {
        int bb = i / 108, k = i % 108;
        g_fh[(size_t)(b0 + bb) * KP + c * 108 + k] = __float2half(sF[bb * 109 + k]);
    }
}

// ---------------------------------------------------------------------------
// Kernel 2: FC1 via mma.sync m16n8k16, single-pass fp16.
// CTA 256x128 (BM=256, BN=128), 512 threads (16 warps 4x4, each 64x32).
// Halves tile-load traffic per output vs 128x128 (L2-bandwidth bound).
// 4-stage cp.async pipeline, one barrier per iteration.
// ---------------------------------------------------------------------------
#define BM 256
#define BN 128
#define BK 32
#define ROWB 80                 // bytes per smem row (40 halfs)
#define A_SZ (BM * ROWB)        // 20480 B
#define B_SZ (BN * ROWB)        // 10240 B
#define ST_A  0
#define ST_B  (A_SZ)
#define ST_SZ (A_SZ + B_SZ)     // 30720 B per stage
#define NSTAGE 4
#define SM_GEMM (NSTAGE * ST_SZ)   // 122880 B

__device__ __forceinline__ void load_chunk(uint32_t sb, int s, int ch,
                                           int m0, int n0, int tid)
{
    const int k0 = ch * BK;
    const uint32_t st = sb + s * ST_SZ;
    // A: 256 rows x 4 quads = 1024 units, 512 threads -> 2 each
    #pragma unroll
    for (int i = 0; i < 2; i++) {
        int u = tid + i * 512;
        int r = u >> 2, cq = u & 3;
        CP16(st + ST_A + r * ROWB + cq * 16,
             g_fh + (size_t)(m0 + r) * KP + k0 + cq * 8);
    }
    // B: 128 rows x 4 quads = 512 units, 1 each
    {
        int r = tid >> 2, cq = tid & 3;
        CP16(st + ST_B + r * ROWB + cq * 16,
             g_w1h + (size_t)(n0 + r) * KP + k0 + cq * 8);
    }
}

__device__ __forceinline__ void compute_chunk(uint32_t st, float acc[4][4][4],
                                              int warp_m, int warp_n, int lane)
{
    const int arow  = warp_m * 64 + (lane & 15);
    const int acol0 = (lane >> 4) * 8;            // halfs
    const int brow  = warp_n * 32 + (lane & 7);
    const int bcol0 = ((lane >> 3) & 1) * 8;      // halfs

    #pragma unroll
    for (int ks = 0; ks < 2; ks++) {
        uint32_t a[4][4], b[4][2];
        #pragma unroll
        for (int mt = 0; mt < 4; mt++) {
            uint32_t ad = st + ST_A + (uint32_t)(arow + mt * 16) * ROWB
                        + (uint32_t)(ks * 16 + acol0) * 2;
            LDSM4(a[mt], ad);
        }
        #pragma unroll
        for (int nt = 0; nt < 4; nt++) {
            uint32_t bd = st + ST_B + (uint32_t)(brow + nt * 8) * ROWB
                        + (uint32_t)(ks * 16 + bcol0) * 2;
            LDSM2(b[nt], bd);
        }
        #pragma unroll
        for (int mt = 0; mt < 4; mt++)
            #pragma unroll
            for (int nt = 0; nt < 4; nt++)
                mma16816(acc[mt][nt], a[mt], b[nt]);
    }
}

__global__ __launch_bounds__(512, 1)
void gemm1_mma_kernel(const float* __restrict__ fb1)
{
    extern __shared__ __align__(128) char smem[];
    const uint32_t sb = smem_u32(smem);
    const int tid    = threadIdx.x;
    const int wid    = tid >> 5;
    const int lane   = tid & 31;
    const int warp_m = wid >> 2;      // 0..3
    const int warp_n = wid & 3;       // 0..3
    const int n0 = blockIdx.x * BN;
    const int m0 = blockIdx.y * BM;

    float acc[4][4][4];
    #pragma unroll
    for (int mt = 0; mt < 4; mt++)
        #pragma unroll
        for (int nt = 0; nt < 4; nt++)
            #pragma unroll
            for (int q = 0; q < 4; q++) acc[mt][nt][q] = 0.f;

    const int NCHUNK = KP / BK;       // 224

    load_chunk(sb, 0, 0, m0, n0, tid); CP_COMMIT();
    load_chunk(sb, 1, 1, m0, n0, tid); CP_COMMIT();
    load_chunk(sb, 2, 2, m0, n0, tid); CP_COMMIT();

    int s = 0;
    for (int ch = 0; ch < NCHUNK; ch++) {
        CP_WAIT2();                   // stage `ch` complete (<=2 newer pending)
        __syncthreads();              // data visible to all warps; also orders
                                      // prior-iteration reads before this refill
        compute_chunk(sb + s * ST_SZ, acc, warp_m, warp_n, lane);
        if (ch + 3 < NCHUNK) {
            load_chunk(sb, (s + 3) & 3, ch + 3, m0, n0, tid);
        }
        CP_COMMIT();                  // unconditional: keeps wait_group invariant
        s = (s + 1) & 3;
    }

    // Epilogue: bias + relu, fp32 stores
    const int g  = lane >> 2;
    const int tq = lane & 3;
    #pragma unroll
    for (int mt = 0; mt < 4; mt++) {
        const int r0 = m0 + warp_m * 64 + mt * 16 + g;
        #pragma unroll
        for (int nt = 0; nt < 4; nt++) {
            const int n = n0 + warp_n * 32 + nt * 8 + tq * 2;
            if (n < HID) {
                float b0 = __ldg(fb1 + n);
                float b1 = __ldg(fb1 + n + 1);
                float2 v0, v1;
                v0.x = fmaxf(acc[mt][nt][0] + b0, 0.f);
                v0.y = fmaxf(acc[mt][nt][1] + b1, 0.f);
                v1.x = fmaxf(acc[mt][nt][2] + b0, 0.f);
                v1.y = fmaxf(acc[mt][nt][3] + b1, 0.f);
                *(float2*)(g_h + (size_t)r0 * HID + n)       = v0;
                *(float2*)(g_h + (size_t)(r0 + 8) * HID + n) = v1;
            }
        }
    }
}

// ---------------------------------------------------------------------------
// Kernel 3: FC2 (warp per batch row)
// ---------------------------------------------------------------------------
__global__ __launch_bounds__(256)
void gemm2_kernel(const float* __restrict__ W2, const float* __restrict__ b2,
                  float* __restrict__ out)
{
    const int gwarp = (blockIdx.x * blockDim.x + threadIdx.x) >> 5;
    const int lane  = threadIdx.x & 31;
    if (gwarp >= BATCH) return;

    const float* hrow = g_h + (size_t)gwarp * HID;
    float acc[NOUT];
    #pragma unroll
    for (int n = 0; n < NOUT; n++) acc[n] = 0.f;

    for (int k = lane; k < HID; k += 32) {
        float hv = hrow[k];
        #pragma unroll
        for (int n = 0; n < NOUT; n++) acc[n] += hv * W2[n * HID + k];
    }
    #pragma unroll
    for (int n = 0; n < NOUT; n++) {
        #pragma unroll
        for (int off = 16; off > 0; off >>= 1)
            acc[n] += __shfl_down_sync(0xffffffffu, acc[n], off);
    }
    if (lane == 0) {
        #pragma unroll
        for (int n = 0; n < NOUT; n++)
            out[(size_t)gwarp * NOUT + n] = acc[n] + b2[n];
    }
}

// ---------------------------------------------------------------------------
extern "C" void kernel_launch(void* const* d_in, const int* in_sizes, int n_in,
                              void* d_out, int out_size)
{
    const float* x   = (const float*)d_in[0];
    const float* hw1 = (const float*)d_in[1];
    const float* hb1 = (const float*)d_in[2];
    const float* hw2 = (const float*)d_in[3];
    const float* hb2 = (const float*)d_in[4];
    const float* hw3 = (const float*)d_in[5];
    const float* hb3 = (const float*)d_in[6];
    const float* lw1 = (const float*)d_in[7];
    const float* lb1 = (const float*)d_in[8];
    const float* lw2 = (const float*)d_in[9];
    const float* lb2 = (const float*)d_in[10];
    const float* lw3 = (const float*)d_in[11];
    const float* lb3 = (const float*)d_in[12];
    const float* fw1 = (const float*)d_in[13];
    const float* fb1 = (const float*)d_in[14];
    const float* fw2 = (const float*)d_in[15];
    const float* fb2 = (const float*)d_in[16];
    float* out = (float*)d_out;

    cudaFuncSetAttribute(gemm1_mma_kernel,
                         cudaFuncAttributeMaxDynamicSharedMemorySize, SM_GEMM);
    cudaFuncSetAttribute(feats_kernel,
                         cudaFuncAttributeMaxDynamicSharedMemorySize, SM_FEATS);

    // 0) transpose x -> (c,l,b)
    transpose_kernel<<<BATCH / 32, 256>>>(x);

    // 0b) convert fw1 to fp16 (padded)
    {
        size_t tot = (size_t)HID * FEAT;
        int blocks = (int)((tot + 255) / 256);
        wsplit_kernel<<<blocks, 256>>>(fw1);
    }

    // 1) conv branches -> g_fh
    dim3 g1(C_CH, BATCH / 32);
    feats_kernel<<<g1, 256, SM_FEATS>>>(hw1, hb1, hw2, hb2, hw3, hb3,
                                        lw1, lb1, lw2, lb2, lw3, lb3);

    // 2) FC1 tensor-core GEMM -> g_h
    dim3 g2(NP / BN, BATCH / BM);
    gemm1_mma_kernel<<<g2, 512, SM_GEMM>>>(fb1);

    // 3) FC2 -> out
    gemm2_kernel<<<BATCH / 8, 256>>>(fw2, fb2, out);
}

// round 14
// speedup vs baseline: 1.4161x; 1.4161x over previous
#include <cuda_runtime.h>
#include <cuda_fp16.h>
#include <cstdint>
#include <cstddef>

#define C_CH 66
#define L_IN 100
#define BATCH 4096
#define FEAT 7128          // 9 * 66 * 12
#define KP   7168          // FEAT padded to 64
#define HID  1936
#define NP   2048          // HID padded to 128
#define NOUT 14

// ---------------------------------------------------------------------------
// Device-global scratch (allocation-free rule). .bss => zero-initialized; pad
// regions are never written, so K/N zero-padding is free and deterministic.
// ---------------------------------------------------------------------------
__device__ float  g_xt[(size_t)C_CH * L_IN * BATCH];   // x transposed (c,l,b)
__device__ __half g_fh[(size_t)BATCH * KP];            // feats (fp16)
__device__ __half g_w1h[(size_t)NP * KP];              // fw1 (fp16, padded)
__device__ float  g_h[(size_t)BATCH * HID];            // FC1 output

// ---------------------------------------------------------------------------
// PTX helpers (sm_80-era -> compile for plain compute_103)
// ---------------------------------------------------------------------------
__device__ __forceinline__ uint32_t smem_u32(const void* p) {
    uint32_t a;
    asm("{ .reg .u64 t; cvta.to.shared.u64 t, %1; cvt.u32.u64 %0, t; }" : "=r"(a) : "l"(p));
    return a;
}

#define CP16(saddr, gptr) \
    asm volatile("cp.async.cg.shared.global [%0], [%1], 16;" :: "r"(saddr), "l"(gptr) : "memory")
#define CP_COMMIT() asm volatile("cp.async.commit_group;" ::: "memory")
#define CP_WAIT2()  asm volatile("cp.async.wait_group 2;" ::: "memory")

#define LDSM4(r, addr) \
    asm volatile("ldmatrix.sync.aligned.m8n8.x4.shared.b16 {%0,%1,%2,%3}, [%4];" \
                 : "=r"((r)[0]), "=r"((r)[1]), "=r"((r)[2]), "=r"((r)[3]) : "r"(addr))
#define LDSM2(r, addr) \
    asm volatile("ldmatrix.sync.aligned.m8n8.x2.shared.b16 {%0,%1}, [%2];" \
                 : "=r"((r)[0]), "=r"((r)[1]) : "r"(addr))

__device__ __forceinline__ void mma16816(float* c, const uint32_t* a, const uint32_t* b) {
    asm volatile(
        "mma.sync.aligned.m16n8k16.row.col.f32.f16.f16.f32 "
        "{%0,%1,%2,%3}, {%4,%5,%6,%7}, {%8,%9}, {%0,%1,%2,%3};"
        : "+f"(c[0]), "+f"(c[1]), "+f"(c[2]), "+f"(c[3])
        : "r"(a[0]), "r"(a[1]), "r"(a[2]), "r"(a[3]), "r"(b[0]), "r"(b[1]));
}

// ---------------------------------------------------------------------------
// Kernel 0: transpose x (B,L,C) -> g_xt (C,L,B), tiled for coalescing.
// ---------------------------------------------------------------------------
__global__ __launch_bounds__(256)
void transpose_kernel(const float* __restrict__ x)
{
    __shared__ float tile[32][269];    // pad 264->269 (odd stride: conflict-free)
    const int b0 = blockIdx.x * 32;
    const int wid  = threadIdx.x >> 5;
    const int lane = threadIdx.x & 31;

    for (int l0 = 0; l0 < L_IN; l0 += 4) {
        for (int idx = threadIdx.x; idx < 32 * 264; idx += 256) {
            int bb = idx / 264, j = idx % 264;
            tile[bb][j] = x[((size_t)(b0 + bb) * L_IN + l0) * C_CH + j];
        }
        __syncthreads();
        for (int j = wid; j < 264; j += 8) {
            int lrel = j / C_CH, c = j % C_CH;
            g_xt[((size_t)c * L_IN + l0 + lrel) * BATCH + b0 + lane] = tile[lane][j];
        }
        __syncthreads();
    }
}

// ---------------------------------------------------------------------------
// Kernel 0b: convert fw1 to fp16 (padded to KP stride)
// ---------------------------------------------------------------------------
__global__ __launch_bounds__(256)
void wsplit_kernel(const float* __restrict__ fw1)
{
    size_t idx = (size_t)blockIdx.x * 256 + threadIdx.x;
    if (idx >= (size_t)HID * FEAT) return;
    int n = (int)(idx / FEAT);
    int k = (int)(idx % FEAT);
    g_w1h[(size_t)n * KP + k] = __float2half(fw1[idx]);
}

// ---------------------------------------------------------------------------
// Kernel 1: conv branches (R11 sliding-window inner loops, unchanged) with
// fp16 P1/P2 intermediates: smem 93KB -> ~60KB => 3 CTAs/SM for stall hiding.
// ---------------------------------------------------------------------------

// smem weight layout offsets (floats)
#define O_HW1 0
#define O_HB1 56
#define O_HW2 64
#define O_HB2 288
#define O_HW3 292
#define O_HB3 404
#define O_LW1 408
#define O_LB1 432
#define O_LW2 440
#define O_LB2 536
#define O_LW3 540
#define O_LB3 588
#define W_TOT 592

// dynamic smem byte offsets
#define B_W   0                          // 592 floats = 2368 B
#define B_S   (B_W + W_TOT * 4)          // 100x32 fp32 = 12800 B
#define B_P1  (B_S + 100 * 32 * 4)       // 8x50x32 fp16 = 25600 B
#define B_P2  (B_P1 + 8 * 50 * 32 * 2)   // 4x25x32 fp16 = 6400 B
#define B_SF  (B_P2 + 4 * 25 * 32 * 2)   // 32x109 fp32 = 13952 B
#define SM_FEATS (B_SF + 32 * 109 * 4)   // 61120 B -> 3 CTAs/SM

// layer1: 1 -> 8 channels, warp w handles out-channel o = w. S[100] -> P1[8][50] (fp16).
template<int K, int PAD>
__device__ __forceinline__ void conv1_sl(
    const float* __restrict__ S, __half* __restrict__ P1,
    const float* __restrict__ W, const float* __restrict__ Bv,
    int o, int lane)
{
    float wr[K], win[K];
    #pragma unroll
    for (int j = 0; j < K; j++) wr[j] = W[o * K + j];
    const float bias = Bv[o];
    #pragma unroll
    for (int j = 0; j < K; j++) {
        int p = j - PAD;
        win[j] = (p >= 0) ? S[p * 32 + lane] : 0.f;
    }
    for (int t = 0; t < 50; t++) {
        float r0 = bias;
        #pragma unroll
        for (int j = 0; j < K; j++) r0 += wr[j] * win[j];
        int nx0 = 2 * t + K - PAD;
        float nv0 = (nx0 < 100) ? S[nx0 * 32 + lane] : 0.f;
        #pragma unroll
        for (int j = 0; j < K - 1; j++) win[j] = win[j + 1];
        win[K - 1] = nv0;

        float r1 = bias;
        #pragma unroll
        for (int j = 0; j < K; j++) r1 += wr[j] * win[j];
        int nx1 = 2 * t + 1 + K - PAD;
        float nv1 = (nx1 < 100) ? S[nx1 * 32 + lane] : 0.f;
        #pragma unroll
        for (int j = 0; j < K - 1; j++) win[j] = win[j + 1];
        win[K - 1] = nv1;

        P1[(o * 50 + t) * 32 + lane] =
            __float2half(0.5f * (fmaxf(r0, 0.f) + fmaxf(r1, 0.f)));
    }
}

// layers 2/3: CIN -> 4 channels (fp16 input), warp handles (o, [t0, t0+TN)).
template<int K, int PAD, int CIN, int LIN, int TN>
__device__ __forceinline__ void convN_sl(
    const __half* __restrict__ IN, const float* __restrict__ W,
    int o, int t0, int lane, float* __restrict__ acc0, float* __restrict__ acc1)
{
    constexpr int CH = 4;
    #pragma unroll
    for (int pass = 0; pass < CIN / CH; pass++) {
        float wr[CH][K], win[CH][K];
        #pragma unroll
        for (int ii = 0; ii < CH; ii++) {
            const int i = pass * CH + ii;
            #pragma unroll
            for (int j = 0; j < K; j++) wr[ii][j] = W[(o * CIN + i) * K + j];
            #pragma unroll
            for (int j = 0; j < K; j++) {
                int p = 2 * t0 - PAD + j;
                win[ii][j] = (p >= 0 && p < LIN)
                           ? __half2float(IN[(i * LIN + p) * 32 + lane]) : 0.f;
            }
        }
        #pragma unroll
        for (int tt = 0; tt < TN; tt++) {
            float r0 = 0.f;
            #pragma unroll
            for (int ii = 0; ii < CH; ii++)
                #pragma unroll
                for (int j = 0; j < K; j++) r0 += wr[ii][j] * win[ii][j];
            acc0[tt] += r0;
            {
                int nx = 2 * (t0 + tt) + K - PAD;
                #pragma unroll
                for (int ii = 0; ii < CH; ii++) {
                    const int i = pass * CH + ii;
                    float nv = (nx < LIN)
                             ? __half2float(IN[(i * LIN + nx) * 32 + lane]) : 0.f;
                    #pragma unroll
                    for (int j = 0; j < K - 1; j++) win[ii][j] = win[ii][j + 1];
                    win[ii][K - 1] = nv;
                }
            }
            float r1 = 0.f;
            #pragma unroll
            for (int ii = 0; ii < CH; ii++)
                #pragma unroll
                for (int j = 0; j < K; j++) r1 += wr[ii][j] * win[ii][j];
            acc1[tt] += r1;
            {
                int nx = 2 * (t0 + tt) + 1 + K - PAD;
                #pragma unroll
                for (int ii = 0; ii < CH; ii++) {
                    const int i = pass * CH + ii;
                    float nv = (nx < LIN)
                             ? __half2float(IN[(i * LIN + nx) * 32 + lane]) : 0.f;
                    #pragma unroll
                    for (int j = 0; j < K - 1; j++) win[ii][j] = win[ii][j + 1];
                    win[ii][K - 1] = nv;
                }
            }
        }
    }
}

// layer2 wrapper: P1[8][50] -> P2[4][25] (both fp16)
template<int K, int PAD, int TN>
__device__ __forceinline__ void conv2_run(
    const __half* __restrict__ P1, __half* __restrict__ P2,
    const float* __restrict__ W, const float* __restrict__ Bv,
    int o, int t0, int lane)
{
    float a0[TN], a1[TN];
    #pragma unroll
    for (int i = 0; i < TN; i++) { a0[i] = 0.f; a1[i] = 0.f; }
    convN_sl<K, PAD, 8, 50, TN>(P1, W, o, t0, lane, a0, a1);
    const float bias = Bv[o];
    #pragma unroll
    for (int tt = 0; tt < TN; tt++)
        P2[(o * 25 + t0 + tt) * 32 + lane] =
            __float2half(0.5f * (fmaxf(a0[tt] + bias, 0.f) + fmaxf(a1[tt] + bias, 0.f)));
}

// layer3 wrapper: P2[4][25] (fp16) -> sF[lane][base + o*12 + t] (fp32)
template<int K, int PAD, int TN>
__device__ __forceinline__ void conv3_run(
    const __half* __restrict__ P2, float* __restrict__ sF,
    const float* __restrict__ W, const float* __restrict__ Bv,
    int o, int t0, int lane, int base)
{
    float a0[TN], a1[TN];
    #pragma unroll
    for (int i = 0; i < TN; i++) { a0[i] = 0.f; a1[i] = 0.f; }
    convN_sl<K, PAD, 4, 25, TN>(P2, W, o, t0, lane, a0, a1);
    const float bias = Bv[o];
    #pragma unroll
    for (int tt = 0; tt < TN; tt++)
        sF[lane * 109 + base + o * 12 + t0 + tt] =
            0.5f * (fmaxf(a0[tt] + bias, 0.f) + fmaxf(a1[tt] + bias, 0.f));
}

__global__ __launch_bounds__(256, 3)
void feats_kernel(const float* __restrict__ hw1, const float* __restrict__ hb1,
                  const float* __restrict__ hw2, const float* __restrict__ hb2,
                  const float* __restrict__ hw3, const float* __restrict__ hb3,
                  const float* __restrict__ lw1, const float* __restrict__ lb1,
                  const float* __restrict__ lw2, const float* __restrict__ lb2,
                  const float* __restrict__ lw3, const float* __restrict__ lb3)
{
    extern __shared__ __align__(16) char smc[];
    float*  sW = (float*)(smc + B_W);
    float*  S  = (float*)(smc + B_S);
    __half* P1 = (__half*)(smc + B_P1);
    __half* P2 = (__half*)(smc + B_P2);
    float*  sF = (float*)(smc + B_SF);

    const int c   = blockIdx.x;
    const int b0  = blockIdx.y * 32;
    const int tid = threadIdx.x;
    const int wid  = tid >> 5;
    const int lane = tid & 31;

    // Phase 1: weights + signal
    { for (int i = tid; i < 56;  i += 256) sW[O_HW1 + i] = hw1[c * 56  + i]; }
    { for (int i = tid; i < 8;   i += 256) sW[O_HB1 + i] = hb1[c * 8   + i]; }
    { for (int i = tid; i < 224; i += 256) sW[O_HW2 + i] = hw2[c * 224 + i]; }
    { for (int i = tid; i < 4;   i += 256) sW[O_HB2 + i] = hb2[c * 4   + i]; }
    { for (int i = tid; i < 112; i += 256) sW[O_HW3 + i] = hw3[c * 112 + i]; }
    { for (int i = tid; i < 4;   i += 256) sW[O_HB3 + i] = hb3[c * 4   + i]; }
    { for (int i = tid; i < 24;  i += 256) sW[O_LW1 + i] = lw1[c * 24  + i]; }
    { for (int i = tid; i < 8;   i += 256) sW[O_LB1 + i] = lb1[c * 8   + i]; }
    { for (int i = tid; i < 96;  i += 256) sW[O_LW2 + i] = lw2[c * 96  + i]; }
    { for (int i = tid; i < 4;   i += 256) sW[O_LB2 + i] = lb2[c * 4   + i]; }
    { for (int i = tid; i < 48;  i += 256) sW[O_LW3 + i] = lw3[c * 48  + i]; }
    { for (int i = tid; i < 4;   i += 256) sW[O_LB3 + i] = lb3[c * 4   + i]; }
    for (int l = wid; l < L_IN; l += 8)
        S[l * 32 + lane] = g_xt[((size_t)c * L_IN + l) * BATCH + b0 + lane];
    __syncthreads();

    const int o4   = wid & 3;
    const int half = wid >> 2;

    // Phase 2: conv1 high
    conv1_sl<7, 3>(S, P1, sW + O_HW1, sW + O_HB1, wid, lane);
    __syncthreads();

    // Phase 3: conv2 high
    if (half == 0) conv2_run<7, 3, 13>(P1, P2, sW + O_HW2, sW + O_HB2, o4, 0,  lane);
    else           conv2_run<7, 3, 12>(P1, P2, sW + O_HW2, sW + O_HB2, o4, 13, lane);
    __syncthreads();

    // Phase 4: conv3 high + conv1 low + residual
    conv3_run<7, 3, 6>(P2, sF, sW + O_HW3, sW + O_HB3, o4, half * 6, lane, 0);
    conv1_sl<3, 1>(S, P1, sW + O_LW1, sW + O_LB1, wid, lane);
    for (int t = wid; t < 12; t += 8) {
        float s = 0.f;
        #pragma unroll
        for (int j = 0; j < 8; j++) s += S[(8 * t + j) * 32 + lane];
        sF[lane * 109 + 96 + t] = 0.125f * s;
    }
    __syncthreads();

    // Phase 5: conv2 low
    if (half == 0) conv2_run<3, 1, 13>(P1, P2, sW + O_LW2, sW + O_LB2, o4, 0,  lane);
    else           conv2_run<3, 1, 12>(P1, P2, sW + O_LW2, sW + O_LB2, o4, 13, lane);
    __syncthreads();

    // Phase 6: conv3 low
    conv3_run<3, 1, 6>(P2, sF, sW + O_LW3, sW + O_LB3, o4, half * 6, lane, 48);
    __syncthreads();

    // Phase 7: coalesced fp16 store
    for (int i = tid; i < 32 * 108; i += 256) {
        int bb = i / 108, k = i % 108;
        g_fh[(size_t)(b0 + bb) * KP + c * 108 + k] = __float2half(sF[bb * 109 + k]);
    }
}

// ---------------------------------------------------------------------------
// Kernel 2: FC1 via mma.sync m16n8k16, single-pass fp16 (R11-verified config).
// CTA 128x128, BK=32, 256 threads (8 warps: 2x4, each 64x32).
// 4-stage cp.async pipeline, one barrier per iteration.
// ---------------------------------------------------------------------------
#define BM 128
#define BN 128
#define BK 32
#define ROWB 80                 // bytes per smem row (40 halfs)
#define MAT_SZ (128 * ROWB)     // 10240 B per matrix tile
#define ST_A  0
#define ST_B  (MAT_SZ)
#define ST_SZ (2 * MAT_SZ)      // 20480 B per stage
#define NSTAGE 4
#define SM_GEMM (NSTAGE * ST_SZ)   // 81920 B

__device__ __forceinline__ void load_chunk(uint32_t sb, int s, int ch,
                                           int m0, int n0, int tid)
{
    const int k0 = ch * BK;
    const uint32_t st = sb + s * ST_SZ;
    #pragma unroll
    for (int i = 0; i < 2; i++) {
        int u = tid + i * 256;          // 0..511
        int r = u >> 2;                 // row 0..127
        int cq = u & 3;                 // 16B quad within row
        uint32_t so = r * ROWB + cq * 16;
        size_t ga = (size_t)(m0 + r) * KP + k0 + cq * 8;
        size_t gb = (size_t)(n0 + r) * KP + k0 + cq * 8;
        CP16(st + ST_A + so, g_fh  + ga);
        CP16(st + ST_B + so, g_w1h + gb);
    }
}

__device__ __forceinline__ void compute_chunk(uint32_t st, float acc[4][4][4],
                                              int warp_m, int warp_n, int lane)
{
    const int arow  = warp_m * 64 + (lane & 15);
    const int acol0 = (lane >> 4) * 8;            // halfs
    const int brow  = warp_n * 32 + (lane & 7);
    const int bcol0 = ((lane >> 3) & 1) * 8;      // halfs

    #pragma unroll
    for (int ks = 0; ks < 2; ks++) {
        uint32_t a[4][4], b[4][2];
        #pragma unroll
        for (int mt = 0; mt < 4; mt++) {
            uint32_t ad = st + ST_A + (uint32_t)(arow + mt * 16) * ROWB
                        + (uint32_t)(ks * 16 + acol0) * 2;
            LDSM4(a[mt], ad);
        }
        #pragma unroll
        for (int nt = 0; nt < 4; nt++) {
            uint32_t bd = st + ST_B + (uint32_t)(brow + nt * 8) * ROWB
                        + (uint32_t)(ks * 16 + bcol0) * 2;
            LDSM2(b[nt], bd);
        }
        #pragma unroll
        for (int mt = 0; mt < 4; mt++)
            #pragma unroll
            for (int nt = 0; nt < 4; nt++)
                mma16816(acc[mt][nt], a[mt], b[nt]);
    }
}

__global__ __launch_bounds__(256, 2)
void gemm1_mma_kernel(const float* __restrict__ fb1)
{
    extern __shared__ __align__(128) char smem[];
    const uint32_t sb = smem_u32(smem);
    const int tid    = threadIdx.x;
    const int wid    = tid >> 5;
    const int lane   = tid & 31;
    const int warp_m = wid >> 2;      // 0..1
    const int warp_n = wid & 3;       // 0..3
    const int n0 = blockIdx.x * BN;
    const int m0 = blockIdx.y * BM;

    float acc[4][4][4];
    #pragma unroll
    for (int mt = 0; mt < 4; mt++)
        #pragma unroll
        for (int nt = 0; nt < 4; nt++)
            #pragma unroll
            for (int q = 0; q < 4; q++) acc[mt][nt][q] = 0.f;

    const int NCHUNK = KP / BK;       // 224

    load_chunk(sb, 0, 0, m0, n0, tid); CP_COMMIT();
    load_chunk(sb, 1, 1, m0, n0, tid); CP_COMMIT();
    load_chunk(sb, 2, 2, m0, n0, tid); CP_COMMIT();

    int s = 0;
    for (int ch = 0; ch < NCHUNK; ch++) {
        CP_WAIT2();                   // stage `ch` complete (<=2 newer pending)
        __syncthreads();              // data visible to all warps; also orders
                                      // prior-iteration reads before this refill
        compute_chunk(sb + s * ST_SZ, acc, warp_m, warp_n, lane);
        if (ch + 3 < NCHUNK) {
            load_chunk(sb, (s + 3) & 3, ch + 3, m0, n0, tid);
        }
        CP_COMMIT();                  // unconditional: keeps wait_group invariant
        s = (s + 1) & 3;
    }

    // Epilogue: bias + relu, fp32 stores
    const int g  = lane >> 2;
    const int tq = lane & 3;
    #pragma unroll
    for (int mt = 0; mt < 4; mt++) {
        const int r0 = m0 + warp_m * 64 + mt * 16 + g;
        #pragma unroll
        for (int nt = 0; nt < 4; nt++) {
            const int n = n0 + warp_n * 32 + nt * 8 + tq * 2;
            if (n < HID) {
                float b0 = __ldg(fb1 + n);
                float b1 = __ldg(fb1 + n + 1);
                float2 v0, v1;
                v0.x = fmaxf(acc[mt][nt][0] + b0, 0.f);
                v0.y = fmaxf(acc[mt][nt][1] + b1, 0.f);
                v1.x = fmaxf(acc[mt][nt][2] + b0, 0.f);
                v1.y = fmaxf(acc[mt][nt][3] + b1, 0.f);
                *(float2*)(g_h + (size_t)r0 * HID + n)       = v0;
                *(float2*)(g_h + (size_t)(r0 + 8) * HID + n) = v1;
            }
        }
    }
}

// ---------------------------------------------------------------------------
// Kernel 3: FC2 (warp per batch row)
// ---------------------------------------------------------------------------
__global__ __launch_bounds__(256)
void gemm2_kernel(const float* __restrict__ W2, const float* __restrict__ b2,
                  float* __restrict__ out)
{
    const int gwarp = (blockIdx.x * blockDim.x + threadIdx.x) >> 5;
    const int lane  = threadIdx.x & 31;
    if (gwarp >= BATCH) return;

    const float* hrow = g_h + (size_t)gwarp * HID;
    float acc[NOUT];
    #pragma unroll
    for (int n = 0; n < NOUT; n++) acc[n] = 0.f;

    for (int k = lane; k < HID; k += 32) {
        float hv = hrow[k];
        #pragma unroll
        for (int n = 0; n < NOUT; n++) acc[n] += hv * W2[n * HID + k];
    }
    #pragma unroll
    for (int n = 0; n < NOUT; n++) {
        #pragma unroll
        for (int off = 16; off > 0; off >>= 1)
            acc[n] += __shfl_down_sync(0xffffffffu, acc[n], off);
    }
    if (lane == 0) {
        #pragma unroll
        for (int n = 0; n < NOUT; n++)
            out[(size_t)gwarp * NOUT + n] = acc[n] + b2[n];
    }
}

// ---------------------------------------------------------------------------
extern "C" void kernel_launch(void* const* d_in, const int* in_sizes, int n_in,
                              void* d_out, int out_size)
{
    const float* x   = (const float*)d_in[0];
    const float* hw1 = (const float*)d_in[1];
    const float* hb1 = (const float*)d_in[2];
    const float* hw2 = (const float*)d_in[3];
    const float* hb2 = (const float*)d_in[4];
    const float* hw3 = (const float*)d_in[5];
    const float* hb3 = (const float*)d_in[6];
    const float* lw1 = (const float*)d_in[7];
    const float* lb1 = (const float*)d_in[8];
    const float* lw2 = (const float*)d_in[9];
    const float* lb2 = (const float*)d_in[10];
    const float* lw3 = (const float*)d_in[11];
    const float* lb3 = (const float*)d_in[12];
    const float* fw1 = (const float*)d_in[13];
    const float* fb1 = (const float*)d_in[14];
    const float* fw2 = (const float*)d_in[15];
    const float* fb2 = (const float*)d_in[16];
    float* out = (float*)d_out;

    cudaFuncSetAttribute(gemm1_mma_kernel,
                         cudaFuncAttributeMaxDynamicSharedMemorySize, SM_GEMM);
    cudaFuncSetAttribute(feats_kernel,
                         cudaFuncAttributeMaxDynamicSharedMemorySize, SM_FEATS);

    // 0) transpose x -> (c,l,b)
    transpose_kernel<<<BATCH / 32, 256>>>(x);

    // 0b) convert fw1 to fp16 (padded)
    {
        size_t tot = (size_t)HID * FEAT;
        int blocks = (int)((tot + 255) / 256);
        wsplit_kernel<<<blocks, 256>>>(fw1);
    }

    // 1) conv branches -> g_fh
    dim3 g1(C_CH, BATCH / 32);
    feats_kernel<<<g1, 256, SM_FEATS>>>(hw1, hb1, hw2, hb2, hw3, hb3,
                                        lw1, lb1, lw2, lb2, lw3, lb3);

    // 2) FC1 tensor-core GEMM -> g_h
    dim3 g2(NP / BN, BATCH / BM);
    gemm1_mma_kernel<<<g2, 256, SM_GEMM>>>(fb1);

    // 3) FC2 -> out
    gemm2_kernel<<<BATCH / 8, 256>>>(fw2, fb2, out);
}

// round 16
// speedup vs baseline: 1.8237x; 1.2878x over previous
#include <cuda_runtime.h>
#include <cuda_fp16.h>
#include <cstdint>
#include <cstddef>

#define C_CH 66
#define L_IN 100
#define BATCH 4096
#define FEAT 7128          // 9 * 66 * 12
#define KP   7168          // FEAT padded to 64
#define HID  1936
#define NP   2048          // HID padded to 128
#define NOUT 14

// ---------------------------------------------------------------------------
// Device-global scratch (allocation-free rule). .bss => zero-initialized; pad
// regions are never written, so K/N zero-padding is free and deterministic.
// ---------------------------------------------------------------------------
__device__ float  g_xt[(size_t)C_CH * L_IN * BATCH];   // x transposed (c,l,b)
__device__ __half g_fh[(size_t)BATCH * KP];            // feats (fp16)
__device__ __half g_w1h[(size_t)NP * KP];              // fw1 (fp16, padded)
__device__ float  g_h[(size_t)BATCH * HID];            // FC1 output

// ---------------------------------------------------------------------------
// PTX helpers (sm_80-era -> compile for plain compute_103)
// ---------------------------------------------------------------------------
__device__ __forceinline__ uint32_t smem_u32(const void* p) {
    uint32_t a;
    asm("{ .reg .u64 t; cvta.to.shared.u64 t, %1; cvt.u32.u64 %0, t; }" : "=r"(a) : "l"(p));
    return a;
}

#define CP16(saddr, gptr) \
    asm volatile("cp.async.cg.shared.global [%0], [%1], 16;" :: "r"(saddr), "l"(gptr) : "memory")
#define CP_COMMIT() asm volatile("cp.async.commit_group;" ::: "memory")
#define CP_WAIT2()  asm volatile("cp.async.wait_group 2;" ::: "memory")

#define LDSM4(r, addr) \
    asm volatile("ldmatrix.sync.aligned.m8n8.x4.shared.b16 {%0,%1,%2,%3}, [%4];" \
                 : "=r"((r)[0]), "=r"((r)[1]), "=r"((r)[2]), "=r"((r)[3]) : "r"(addr))
#define LDSM2(r, addr) \
    asm volatile("ldmatrix.sync.aligned.m8n8.x2.shared.b16 {%0,%1}, [%2];" \
                 : "=r"((r)[0]), "=r"((r)[1]) : "r"(addr))

__device__ __forceinline__ void mma16816(float* c, const uint32_t* a, const uint32_t* b) {
    asm volatile(
        "mma.sync.aligned.m16n8k16.row.col.f32.f16.f16.f32 "
        "{%0,%1,%2,%3}, {%4,%5,%6,%7}, {%8,%9}, {%0,%1,%2,%3};"
        : "+f"(c[0]), "+f"(c[1]), "+f"(c[2]), "+f"(c[3])
        : "r"(a[0]), "r"(a[1]), "r"(a[2]), "r"(a[3]), "r"(b[0]), "r"(b[1]));
}

// ---------------------------------------------------------------------------
// Kernel 0: transpose x (B,L,C) -> g_xt (C,L,B), tiled for coalescing.
// ---------------------------------------------------------------------------
__global__ __launch_bounds__(256)
void transpose_kernel(const float* __restrict__ x)
{
    __shared__ float tile[32][269];    // pad 264->269 (odd stride: conflict-free)
    const int b0 = blockIdx.x * 32;
    const int wid  = threadIdx.x >> 5;
    const int lane = threadIdx.x & 31;

    for (int l0 = 0; l0 < L_IN; l0 += 4) {
        for (int idx = threadIdx.x; idx < 32 * 264; idx += 256) {
            int bb = idx / 264, j = idx % 264;
            tile[bb][j] = x[((size_t)(b0 + bb) * L_IN + l0) * C_CH + j];
        }
        __syncthreads();
        for (int j = wid; j < 264; j += 8) {
            int lrel = j / C_CH, c = j % C_CH;
            g_xt[((size_t)c * L_IN + l0 + lrel) * BATCH + b0 + lane] = tile[lane][j];
        }
        __syncthreads();
    }
}

// ---------------------------------------------------------------------------
// Kernel 0b: convert fw1 to fp16 (padded to KP stride)
// ---------------------------------------------------------------------------
__global__ __launch_bounds__(256)
void wsplit_kernel(const float* __restrict__ fw1)
{
    size_t idx = (size_t)blockIdx.x * 256 + threadIdx.x;
    if (idx >= (size_t)HID * FEAT) return;
    int n = (int)(idx / FEAT);
    int k = (int)(idx % FEAT);
    g_w1h[(size_t)n * KP + k] = __float2half(fw1[idx]);
}

// ---------------------------------------------------------------------------
// Kernel 1: conv branches, HALF2: lane = 2 batches (b0+lane, b0+32+lane).
// R11 sliding-window structure unchanged; scalar type = __half2.
// Block = (channel c, 64 batches). 66 x 64 = 4224 blocks.
// ---------------------------------------------------------------------------

// smem weight layout offsets (floats)
#define O_HW1 0
#define O_HB1 56
#define O_HW2 64
#define O_HB2 288
#define O_HW3 292
#define O_HB3 404
#define O_LW1 408
#define O_LB1 432
#define O_LW2 440
#define O_LB2 536
#define O_LW3 540
#define O_LB3 588
#define W_TOT 592

// dynamic smem byte offsets (all conv arrays are __half2 = 4 B per lane-pair)
#define B_W   0                          // 2368 B
#define B_S   (B_W + W_TOT * 4)          // 100x32 h2 = 12800 B
#define B_P1  (B_S + 100 * 32 * 4)       // 8x50x32 h2 = 51200 B
#define B_P2  (B_P1 + 8 * 50 * 32 * 4)   // 4x25x32 h2 = 12800 B
#define B_SF  (B_P2 + 4 * 25 * 32 * 4)   // 32x109 h2 = 13952 B
#define SM_FEATS (B_SF + 32 * 109 * 4)   // 93120 B -> 2 CTAs/SM

__device__ __forceinline__ __half2 h2zero() { return __float2half2_rn(0.f); }

// pooled pair -> output: 0.5 * (relu(a0+bias) + relu(a1+bias))
__device__ __forceinline__ __half2 pool_relu(__half2 a0, __half2 a1, __half2 bias2)
{
    __half2 z = h2zero();
    __half2 t0 = __hmax2(__hadd2(a0, bias2), z);
    __half2 t1 = __hmax2(__hadd2(a1, bias2), z);
    return __hmul2(__hadd2(t0, t1), __float2half2_rn(0.5f));
}

// layer1: 1 -> 8 channels, warp w handles out-channel o = w. S[100] -> P1[8][50].
template<int K, int PAD>
__device__ __forceinline__ void conv1_sl(
    const __half2* __restrict__ S, __half2* __restrict__ P1,
    const float* __restrict__ W, const float* __restrict__ Bv,
    int o, int lane)
{
    __half2 wr[K], win[K];
    #pragma unroll
    for (int j = 0; j < K; j++) wr[j] = __float2half2_rn(W[o * K + j]);
    const __half2 bias2 = __float2half2_rn(Bv[o]);
    #pragma unroll
    for (int j = 0; j < K; j++) {
        int p = j - PAD;
        win[j] = (p >= 0) ? S[p * 32 + lane] : h2zero();
    }
    for (int t = 0; t < 50; t++) {
        __half2 r0 = h2zero();
        #pragma unroll
        for (int j = 0; j < K; j++) r0 = __hfma2(wr[j], win[j], r0);
        int nx0 = 2 * t + K - PAD;
        __half2 nv0 = (nx0 < 100) ? S[nx0 * 32 + lane] : h2zero();
        #pragma unroll
        for (int j = 0; j < K - 1; j++) win[j] = win[j + 1];
        win[K - 1] = nv0;

        __half2 r1 = h2zero();
        #pragma unroll
        for (int j = 0; j < K; j++) r1 = __hfma2(wr[j], win[j], r1);
        int nx1 = 2 * t + 1 + K - PAD;
        __half2 nv1 = (nx1 < 100) ? S[nx1 * 32 + lane] : h2zero();
        #pragma unroll
        for (int j = 0; j < K - 1; j++) win[j] = win[j + 1];
        win[K - 1] = nv1;

        P1[(o * 50 + t) * 32 + lane] = pool_relu(r0, r1, bias2);
    }
}

// layers 2/3: CIN -> 4 channels, warp handles (o, t-range [t0, t0+TN)).
template<int K, int PAD, int CIN, int LIN, int TN>
__device__ __forceinline__ void convN_sl(
    const __half2* __restrict__ IN, const float* __restrict__ W,
    int o, int t0, int lane, __half2* __restrict__ acc0, __half2* __restrict__ acc1)
{
    constexpr int CH = 4;
    #pragma unroll
    for (int pass = 0; pass < CIN / CH; pass++) {
        __half2 wr[CH][K], win[CH][K];
        #pragma unroll
        for (int ii = 0; ii < CH; ii++) {
            const int i = pass * CH + ii;
            #pragma unroll
            for (int j = 0; j < K; j++) wr[ii][j] = __float2half2_rn(W[(o * CIN + i) * K + j]);
            #pragma unroll
            for (int j = 0; j < K; j++) {
                int p = 2 * t0 - PAD + j;
                win[ii][j] = (p >= 0 && p < LIN) ? IN[(i * LIN + p) * 32 + lane] : h2zero();
            }
        }
        #pragma unroll
        for (int tt = 0; tt < TN; tt++) {
            __half2 r0 = h2zero();
            #pragma unroll
            for (int ii = 0; ii < CH; ii++)
                #pragma unroll
                for (int j = 0; j < K; j++) r0 = __hfma2(wr[ii][j], win[ii][j], r0);
            acc0[tt] = __hadd2(acc0[tt], r0);
            {
                int nx = 2 * (t0 + tt) + K - PAD;
                #pragma unroll
                for (int ii = 0; ii < CH; ii++) {
                    const int i = pass * CH + ii;
                    __half2 nv = (nx < LIN) ? IN[(i * LIN + nx) * 32 + lane] : h2zero();
                    #pragma unroll
                    for (int j = 0; j < K - 1; j++) win[ii][j] = win[ii][j + 1];
                    win[ii][K - 1] = nv;
                }
            }
            __half2 r1 = h2zero();
            #pragma unroll
            for (int ii = 0; ii < CH; ii++)
                #pragma unroll
                for (int j = 0; j < K; j++) r1 = __hfma2(wr[ii][j], win[ii][j], r1);
            acc1[tt] = __hadd2(acc1[tt], r1);
            {
                int nx = 2 * (t0 + tt) + 1 + K - PAD;
                #pragma unroll
                for (int ii = 0; ii < CH; ii++) {
                    const int i = pass * CH + ii;
                    __half2 nv = (nx < LIN) ? IN[(i * LIN + nx) * 32 + lane] : h2zero();
                    #pragma unroll
                    for (int j = 0; j < K - 1; j++) win[ii][j] = win[ii][j + 1];
                    win[ii][K - 1] = nv;
                }
            }
        }
    }
}

// layer2 wrapper: P1[8][50] -> P2[4][25]
template<int K, int PAD, int TN>
__device__ __forceinline__ void conv2_run(
    const __half2* __restrict__ P1, __half2* __restrict__ P2,
    const float* __restrict__ W, const float* __restrict__ Bv,
    int o, int t0, int lane)
{
    __half2 a0[TN], a1[TN];
    #pragma unroll
    for (int i = 0; i < TN; i++) { a0[i] = h2zero(); a1[i] = h2zero(); }
    convN_sl<K, PAD, 8, 50, TN>(P1, W, o, t0, lane, a0, a1);
    const __half2 bias2 = __float2half2_rn(Bv[o]);
    #pragma unroll
    for (int tt = 0; tt < TN; tt++)
        P2[(o * 25 + t0 + tt) * 32 + lane] = pool_relu(a0[tt], a1[tt], bias2);
}

// layer3 wrapper: P2[4][25] -> sF[lane][base + o*12 + t]
template<int K, int PAD, int TN>
__device__ __forceinline__ void conv3_run(
    const __half2* __restrict__ P2, __half2* __restrict__ sF,
    const float* __restrict__ W, const float* __restrict__ Bv,
    int o, int t0, int lane, int base)
{
    __half2 a0[TN], a1[TN];
    #pragma unroll
    for (int i = 0; i < TN; i++) { a0[i] = h2zero(); a1[i] = h2zero(); }
    convN_sl<K, PAD, 4, 25, TN>(P2, W, o, t0, lane, a0, a1);
    const __half2 bias2 = __float2half2_rn(Bv[o]);
    #pragma unroll
    for (int tt = 0; tt < TN; tt++)
        sF[lane * 109 + base + o * 12 + t0 + tt] = pool_relu(a0[tt], a1[tt], bias2);
}

__global__ __launch_bounds__(256, 2)
void feats_kernel(const float* __restrict__ hw1, const float* __restrict__ hb1,
                  const float* __restrict__ hw2, const float* __restrict__ hb2,
                  const float* __restrict__ hw3, const float* __restrict__ hb3,
                  const float* __restrict__ lw1, const float* __restrict__ lb1,
                  const float* __restrict__ lw2, const float* __restrict__ lb2,
                  const float* __restrict__ lw3, const float* __restrict__ lb3)
{
    extern __shared__ __align__(16) char smc[];
    float*   sW = (float*)(smc + B_W);
    __half2* S  = (__half2*)(smc + B_S);
    __half2* P1 = (__half2*)(smc + B_P1);
    __half2* P2 = (__half2*)(smc + B_P2);
    __half2* sF = (__half2*)(smc + B_SF);

    const int c   = blockIdx.x;
    const int b0  = blockIdx.y * 64;
    const int tid = threadIdx.x;
    const int wid  = tid >> 5;
    const int lane = tid & 31;

    // Phase 1: weights (fp32 smem) + signal (packed half2: batches b0+l, b0+32+l)
    { for (int i = tid; i < 56;  i += 256) sW[O_HW1 + i] = hw1[c * 56  + i]; }
    { for (int i = tid; i < 8;   i += 256) sW[O_HB1 + i] = hb1[c * 8   + i]; }
    { for (int i = tid; i < 224; i += 256) sW[O_HW2 + i] = hw2[c * 224 + i]; }
    { for (int i = tid; i < 4;   i += 256) sW[O_HB2 + i] = hb2[c * 4   + i]; }
    { for (int i = tid; i < 112; i += 256) sW[O_HW3 + i] = hw3[c * 112 + i]; }
    { for (int i = tid; i < 4;   i += 256) sW[O_HB3 + i] = hb3[c * 4   + i]; }
    { for (int i = tid; i < 24;  i += 256) sW[O_LW1 + i] = lw1[c * 24  + i]; }
    { for (int i = tid; i < 8;   i += 256) sW[O_LB1 + i] = lb1[c * 8   + i]; }
    { for (int i = tid; i < 96;  i += 256) sW[O_LW2 + i] = lw2[c * 96  + i]; }
    { for (int i = tid; i < 4;   i += 256) sW[O_LB2 + i] = lb2[c * 4   + i]; }
    { for (int i = tid; i < 48;  i += 256) sW[O_LW3 + i] = lw3[c * 48  + i]; }
    { for (int i = tid; i < 4;   i += 256) sW[O_LB3 + i] = lb3[c * 4   + i]; }
    for (int l = wid; l < L_IN; l += 8) {
        const float* src = g_xt + ((size_t)c * L_IN + l) * BATCH + b0;
        S[l * 32 + lane] = __floats2half2_rn(src[lane], src[32 + lane]);
    }
    __syncthreads();

    const int o4   = wid & 3;
    const int half = wid >> 2;

    // Phase 2: conv1 high
    conv1_sl<7, 3>(S, P1, sW + O_HW1, sW + O_HB1, wid, lane);
    __syncthreads();

    // Phase 3: conv2 high
    if (half == 0) conv2_run<7, 3, 13>(P1, P2, sW + O_HW2, sW + O_HB2, o4, 0,  lane);
    else           conv2_run<7, 3, 12>(P1, P2, sW + O_HW2, sW + O_HB2, o4, 13, lane);
    __syncthreads();

    // Phase 4: conv3 high + conv1 low + residual
    conv3_run<7, 3, 6>(P2, sF, sW + O_HW3, sW + O_HB3, o4, half * 6, lane, 0);
    conv1_sl<3, 1>(S, P1, sW + O_LW1, sW + O_LB1, wid, lane);
    for (int t = wid; t < 12; t += 8) {
        __half2 s = h2zero();
        #pragma unroll
        for (int j = 0; j < 8; j++) s = __hadd2(s, S[(8 * t + j) * 32 + lane]);
        sF[lane * 109 + 96 + t] = __hmul2(s, __float2half2_rn(0.125f));
    }
    __syncthreads();

    // Phase 5: conv2 low
    if (half == 0) conv2_run<3, 1, 13>(P1, P2, sW + O_LW2, sW + O_LB2, o4, 0,  lane);
    else           conv2_run<3, 1, 12>(P1, P2, sW + O_LW2, sW + O_LB2, o4, 13, lane);
    __syncthreads();

    // Phase 6: conv3 low
    conv3_run<3, 1, 6>(P2, sF, sW + O_LW3, sW + O_LB3, o4, half * 6, lane, 48);
    __syncthreads();

    // Phase 7: unpack + coalesced fp16 store (two batch planes)
    for (int i = tid; i < 32 * 108; i += 256) {
        int bb = i / 108, k = i % 108;
        __half2 v = sF[bb * 109 + k];
        g_fh[(size_t)(b0 + bb)      * KP + c * 108 + k] = __low2half(v);
        g_fh[(size_t)(b0 + 32 + bb) * KP + c * 108 + k] = __high2half(v);
    }
}

// ---------------------------------------------------------------------------
// Kernel 2: FC1 via mma.sync m16n8k16, single-pass fp16 (R11-verified config).
// CTA 128x128, BK=32, 256 threads (8 warps: 2x4, each 64x32).
// 4-stage cp.async pipeline, one barrier per iteration.
// ---------------------------------------------------------------------------
#define BM 128
#define BN 128
#define BK 32
#define ROWB 80                 // bytes per smem row (40 halfs)
#define MAT_SZ (128 * ROWB)     // 10240 B per matrix tile
#define ST_A  0
#define ST_B  (MAT_SZ)
#define ST_SZ (2 * MAT_SZ)      // 20480 B per stage
#define NSTAGE 4
#define SM_GEMM (NSTAGE * ST_SZ)   // 81920 B

__device__ __forceinline__ void load_chunk(uint32_t sb, int s, int ch,
                                           int m0, int n0, int tid)
{
    const int k0 = ch * BK;
    const uint32_t st = sb + s * ST_SZ;
    #pragma unroll
    for (int i = 0; i < 2; i++) {
        int u = tid + i * 256;          // 0..511
        int r = u >> 2;                 // row 0..127
        int cq = u & 3;                 // 16B quad within row
        uint32_t so = r * ROWB + cq * 16;
        size_t ga = (size_t)(m0 + r) * KP + k0 + cq * 8;
        size_t gb = (size_t)(n0 + r) * KP + k0 + cq * 8;
        CP16(st + ST_A + so, g_fh  + ga);
        CP16(st + ST_B + so, g_w1h + gb);
    }
}

__device__ __forceinline__ void compute_chunk(uint32_t st, float acc[4][4][4],
                                              int warp_m, int warp_n, int lane)
{
    const int arow  = warp_m * 64 + (lane & 15);
    const int acol0 = (lane >> 4) * 8;            // halfs
    const int brow  = warp_n * 32 + (lane & 7);
    const int bcol0 = ((lane >> 3) & 1) * 8;      // halfs

    #pragma unroll
    for (int ks = 0; ks < 2; ks++) {
        uint32_t a[4][4], b[4][2];
        #pragma unroll
        for (int mt = 0; mt < 4; mt++) {
            uint32_t ad = st + ST_A + (uint32_t)(arow + mt * 16) * ROWB
                        + (uint32_t)(ks * 16 + acol0) * 2;
            LDSM4(a[mt], ad);
        }
        #pragma unroll
        for (int nt = 0; nt < 4; nt++) {
            uint32_t bd = st + ST_B + (uint32_t)(brow + nt * 8) * ROWB
                        + (uint32_t)(ks * 16 + bcol0) * 2;
            LDSM2(b[nt], bd);
        }
        #pragma unroll
        for (int mt = 0; mt < 4; mt++)
            #pragma unroll
            for (int nt = 0; nt < 4; nt++)
                mma16816(acc[mt][nt], a[mt], b[nt]);
    }
}

__global__ __launch_bounds__(256, 2)
void gemm1_mma_kernel(const float* __restrict__ fb1)
{
    extern __shared__ __align__(128) char smem[];
    const uint32_t sb = smem_u32(smem);
    const int tid    = threadIdx.x;
    const int wid    = tid >> 5;
    const int lane   = tid & 31;
    const int warp_m = wid >> 2;      // 0..1
    const int warp_n = wid & 3;       // 0..3
    const int n0 = blockIdx.x * BN;
    const int m0 = blockIdx.y * BM;

    float acc[4][4][4];
    #pragma unroll
    for (int mt = 0; mt < 4; mt++)
        #pragma unroll
        for (int nt = 0; nt < 4; nt++)
            #pragma unroll
            for (int q = 0; q < 4; q++) acc[mt][nt][q] = 0.f;

    const int NCHUNK = KP / BK;       // 224

    load_chunk(sb, 0, 0, m0, n0, tid); CP_COMMIT();
    load_chunk(sb, 1, 1, m0, n0, tid); CP_COMMIT();
    load_chunk(sb, 2, 2, m0, n0, tid); CP_COMMIT();

    int s = 0;
    for (int ch = 0; ch < NCHUNK; ch++) {
        CP_WAIT2();                   // stage `ch` complete (<=2 newer pending)
        __syncthreads();              // data visible to all warps; also orders
                                      // prior-iteration reads before this refill
        compute_chunk(sb + s * ST_SZ, acc, warp_m, warp_n, lane);
        if (ch + 3 < NCHUNK) {
            load_chunk(sb, (s + 3) & 3, ch + 3, m0, n0, tid);
        }
        CP_COMMIT();                  // unconditional: keeps wait_group invariant
        s = (s + 1) & 3;
    }

    // Epilogue: bias + relu, fp32 stores
    const int g  = lane >> 2;
    const int tq = lane & 3;
    #pragma unroll
    for (int mt = 0; mt < 4; mt++) {
        const int r0 = m0 + warp_m * 64 + mt * 16 + g;
        #pragma unroll
        for (int nt = 0; nt < 4; nt++) {
            const int n = n0 + warp_n * 32 + nt * 8 + tq * 2;
            if (n < HID) {
                float b0 = __ldg(fb1 + n);
                float b1 = __ldg(fb1 + n + 1);
                float2 v0, v1;
                v0.x = fmaxf(acc[mt][nt][0] + b0, 0.f);
                v0.y = fmaxf(acc[mt][nt][1] + b1, 0.f);
                v1.x = fmaxf(acc[mt][nt][2] + b0, 0.f);
                v1.y = fmaxf(acc[mt][nt][3] + b1, 0.f);
                *(float2*)(g_h + (size_t)r0 * HID + n)       = v0;
                *(float2*)(g_h + (size_t)(r0 + 8) * HID + n) = v1;
            }
        }
    }
}

// ---------------------------------------------------------------------------
// Kernel 3: FC2 (warp per batch row)
// ---------------------------------------------------------------------------
__global__ __launch_bounds__(256)
void gemm2_kernel(const float* __restrict__ W2, const float* __restrict__ b2,
                  float* __restrict__ out)
{
    const int gwarp = (blockIdx.x * blockDim.x + threadIdx.x) >> 5;
    const int lane  = threadIdx.x & 31;
    if (gwarp >= BATCH) return;

    const float* hrow = g_h + (size_t)gwarp * HID;
    float acc[NOUT];
    #pragma unroll
    for (int n = 0; n < NOUT; n++) acc[n] = 0.f;

    for (int k = lane; k < HID; k += 32) {
        float hv = hrow[k];
        #pragma unroll
        for (int n = 0; n < NOUT; n++) acc[n] += hv * W2[n * HID + k];
    }
    #pragma unroll
    for (int n = 0; n < NOUT; n++) {
        #pragma unroll
        for (int off = 16; off > 0; off >>= 1)
            acc[n] += __shfl_down_sync(0xffffffffu, acc[n], off);
    }
    if (lane == 0) {
        #pragma unroll
        for (int n = 0; n < NOUT; n++)
            out[(size_t)gwarp * NOUT + n] = acc[n] + b2[n];
    }
}

// ---------------------------------------------------------------------------
extern "C" void kernel_launch(void* const* d_in, const int* in_sizes, int n_in,
                              void* d_out, int out_size)
{
    const float* x   = (const float*)d_in[0];
    const float* hw1 = (const float*)d_in[1];
    const float* hb1 = (const float*)d_in[2];
    const float* hw2 = (const float*)d_in[3];
    const float* hb2 = (const float*)d_in[4];
    const float* hw3 = (const float*)d_in[5];
    const float* hb3 = (const float*)d_in[6];
    const float* lw1 = (const float*)d_in[7];
    const float* lb1 = (const float*)d_in[8];
    const float* lw2 = (const float*)d_in[9];
    const float* lb2 = (const float*)d_in[10];
    const float* lw3 = (const float*)d_in[11];
    const float* lb3 = (const float*)d_in[12];
    const float* fw1 = (const float*)d_in[13];
    const float* fb1 = (const float*)d_in[14];
    const float* fw2 = (const float*)d_in[15];
    const float* fb2 = (const float*)d_in[16];
    float* out = (float*)d_out;

    cudaFuncSetAttribute(gemm1_mma_kernel,
                         cudaFuncAttributeMaxDynamicSharedMemorySize, SM_GEMM);
    cudaFuncSetAttribute(feats_kernel,
                         cudaFuncAttributeMaxDynamicSharedMemorySize, SM_FEATS);

    // 0) transpose x -> (c,l,b)
    transpose_kernel<<<BATCH / 32, 256>>>(x);

    // 0b) convert fw1 to fp16 (padded)
    {
        size_t tot = (size_t)HID * FEAT;
        int blocks = (int)((tot + 255) / 256);
        wsplit_kernel<<<blocks, 256>>>(fw1);
    }

    // 1) conv branches -> g_fh (half2: 64 batches per block)
    dim3 g1(C_CH, BATCH / 64);
    feats_kernel<<<g1, 256, SM_FEATS>>>(hw1, hb1, hw2, hb2, hw3, hb3,
                                        lw1, lb1, lw2, lb2, lw3, lb3);

    // 2) FC1 tensor-core GEMM -> g_h
    dim3 g2(NP / BN, BATCH / BM);
    gemm1_mma_kernel<<<g2, 256, SM_GEMM>>>(fb1);

    // 3) FC2 -> out
    gemm2_kernel<<<BATCH / 8, 256>>>(fw2, fb2, out);
}